// round 14
// baseline (speedup 1.0000x reference)
#include <cuda_runtime.h>

#define BH_ 16

// gmem scratch
__device__ float4 g_xs4[BH_ * 1024];          // softmaxed x, stride 32 floats
__device__ float  g_sv [BH_ * 128 * 33];      // sorted values, stride 33
__device__ float  g_qA [BH_ * 128 * 33];      // 1 - prefix1(r)     (coeff 0.5u^2)
__device__ float  g_qB [BH_ * 128 * 33];      // 0.5 * prefix2(r)   (coeff u)
__device__ float  g_qC [BH_ * 128 * 33];      // -prefix3(r)/6      (constant)

static const int SMEM_PROJ = (8 * 256 + 32 * 257 + 8 * 32) * 4;            // 42112
// floats: qA/qB/qC/sv 4*4224, xsh 4096, attn 1024, osmp 1024, osm 256, red 64
static const int SMEM_SPL  = (4 * 4224 + 4096 + 1024 + 1024 + 256 + 64) * 4;  // 93440

__device__ __forceinline__ float wmax(float v) {
    #pragma unroll
    for (int o = 16; o > 0; o >>= 1) v = fmaxf(v, __shfl_xor_sync(0xffffffffu, v, o));
    return v;
}
__device__ __forceinline__ float wsum(float v) {
    #pragma unroll
    for (int o = 16; o > 0; o >>= 1) v += __shfl_xor_sync(0xffffffffu, v, o);
    return v;
}

// ---------------------------------------------------------------------------
// K1: in-proj GEMM + softmax + counting-rank tables + out := b_out (bias init).
// grid(32,8), 256 thr.  [R10; g_sv stride now 33]
// ---------------------------------------------------------------------------
__global__ void k_proj(const float* __restrict__ inp,
                       const float* __restrict__ w_in,
                       const float* __restrict__ b_in,
                       const float* __restrict__ b_out,
                       float* __restrict__ out) {
    extern __shared__ float sm[];
    float* xs = sm;                 // [8][256]
    float* ws = sm + 8 * 256;       // [32][257]
    float* ps = ws + 32 * 257;      // [8][32]

    const int t = threadIdx.x, lane = t & 31, wid = t >> 5;
    const int r0 = blockIdx.x * 8, hd = blockIdx.y, c0 = hd * 32;

    {
        const int idx = ((blockIdx.y * 32 + blockIdx.x) << 8) + t;
        out[idx] = b_out[idx & 255];
    }

    #pragma unroll
    for (int f = t; f < 512; f += 256) {
        const int r = f >> 6, kq = f & 63;
        *(float4*)(xs + r * 256 + kq * 4) = *(const float4*)(inp + (r0 + r) * 256 + kq * 4);
    }
    #pragma unroll
    for (int rr = 0; rr < 4; ++rr) {
        const int cc = wid * 4 + rr;
        #pragma unroll
        for (int hh = 0; hh < 2; ++hh) {
            const int k4 = hh * 32 + lane;
            const float4 v = *(const float4*)(w_in + (c0 + cc) * 256 + k4 * 4);
            float* d = ws + cc * 257 + k4 * 4;
            d[0] = v.x; d[1] = v.y; d[2] = v.z; d[3] = v.w;
        }
    }
    __syncthreads();

    const int kh = wid >> 2, rg = wid & 3;
    const float* wrow = ws + lane * 257 + kh * 128;
    float acc[2] = {0.f, 0.f};
    #pragma unroll 8
    for (int kq = 0; kq < 32; ++kq) {
        const float w0 = wrow[4 * kq + 0], w1 = wrow[4 * kq + 1];
        const float w2 = wrow[4 * kq + 2], w3 = wrow[4 * kq + 3];
        #pragma unroll
        for (int rr = 0; rr < 2; ++rr) {
            const float4 x4 = *(const float4*)(xs + (rg * 2 + rr) * 256 + kh * 128 + 4 * kq);
            acc[rr] = fmaf(w0, x4.x, fmaf(w1, x4.y, fmaf(w2, x4.z, fmaf(w3, x4.w, acc[rr]))));
        }
    }
    if (kh == 1) {
        #pragma unroll
        for (int rr = 0; rr < 2; ++rr) ps[(rg * 2 + rr) * 32 + lane] = acc[rr];
    }
    __syncthreads();
    if (kh == 0) {
        const float bb = b_in[c0 + lane];
        float* gxs = (float*)g_xs4;
        #pragma unroll
        for (int rr = 0; rr < 2; ++rr) {
            const float val = acc[rr] + ps[(rg * 2 + rr) * 32 + lane] + bb;
            const float mx = wmax(val);
            float p = __expf(val - mx);
            const float smv = wsum(p);
            p = p / smv;

            const int row = r0 + rg * 2 + rr;
            const int b = row >> 7, s = row & 127;
            const int rowo = (b * 8 + hd) * 128 + s;
            gxs[rowo * 32 + lane] = p;

            const float p2o = p * p, p3o = p2o * p;
            float pre1 = 0.f, pre2 = 0.f, pre3 = 0.f;
            int rank = 0;
            #pragma unroll
            for (int f = 0; f < 32; ++f) {
                const float vf = __shfl_sync(0xffffffffu, p, f);
                const bool below = (vf < p) | ((vf == p) & (f < lane));
                if (below) {
                    const float vf2 = vf * vf;
                    pre1 += vf;
                    pre2 += vf2;
                    pre3 += vf2 * vf;
                    ++rank;
                }
            }
            g_sv[rowo * 33 + rank] = p;
            g_qA[rowo * 33 + rank] = 1.f - pre1;
            g_qB[rowo * 33 + rank] = 0.5f * pre2;
            g_qC[rowo * 33 + rank] = -pre3 * (1.f / 6.f);
            if (rank == 31) {
                g_qA[rowo * 33 + 32] = 0.f;
                g_qB[rowo * 33 + 32] = 0.5f * (pre2 + p2o);
                g_qC[rowo * 33 + 32] = -(pre3 + p3o) * (1.f / 6.f);
            }
        }
    }
}

// ---------------------------------------------------------------------------
// K2: spline + softmax + AV + out-projection. grid(16,16), 1024 thr (32 warps).
// Warp = (row rg, j-quarter q); LANE = j. No butterfly; acc lives in lane j.
// 64 warps/SM at 2 blocks.
// ---------------------------------------------------------------------------
__global__ void __launch_bounds__(1024, 2) k_spline(const float* __restrict__ w_out,
                                                    float* __restrict__ out) {
    extern __shared__ float sm_raw[];
    float* qA   = sm_raw;                     // [128*33]  (qA+qB reused as wsm)
    float* qB   = qA + 4224;
    float* qC   = qB + 4224;
    float* sv   = qC + 4224;                  // [128][33]
    float* xsh  = sv + 4224;                  // [128][32]
    float* attn = xsh + 4096;                 // [8][128]
    float* osmp = attn + 1024;                // [4][8][32]
    float* osm  = osmp + 1024;                // [8][32]
    float* redm = osm + 256;                  // [8][4]
    float* reds = redm + 32;                  // [8][4]

    const int t = threadIdx.x, lane = t & 31, wid = t >> 5;
    const int rg = wid & 7, q = wid >> 3;     // row-group, j-quarter
    const int bh = blockIdx.y;
    const int bq = bh >> 3, hq = bh & 7;

    {
        const float4* a = (const float4*)(g_qA + bh * 4224);
        const float4* b = (const float4*)(g_qB + bh * 4224);
        const float4* c = (const float4*)(g_qC + bh * 4224);
        const float4* sp = (const float4*)(g_sv + bh * 4224);
        for (int f = t; f < 1056; f += 1024) {
            *(float4*)(qA + 4 * f) = a[f];
            *(float4*)(qB + 4 * f) = b[f];
            *(float4*)(qC + 4 * f) = c[f];
            *(float4*)(sv + 4 * f) = sp[f];
        }
        const float4* xp = g_xs4 + bh * 1024;
        for (int f = t; f < 1024; f += 1024) *(float4*)(xsh + 4 * f) = xp[f];
    }
    __syncthreads();

    const int i = blockIdx.x * 8 + rg;
    const int j = q * 32 + lane;
    const float* svj = sv + j * 33;
    const int jo = j * 33;
    const float* urow = xsh + i * 32;

    float acc = 0.f;
    #pragma unroll 2
    for (int e = 0; e < 32; ++e) {
        const float u  = urow[e];             // broadcast LDS
        const float uu = u * u;
        const float u2 = 0.5f * uu;
        const float u3 = uu * u * (1.f / 6.f);
        int r = (svj[15] < u) ? 16 : 0;
        r += (svj[r + 7] < u) ? 8 : 0;
        r += (svj[r + 3] < u) ? 4 : 0;
        r += (svj[r + 1] < u) ? 2 : 0;
        r += (svj[r]     < u) ? 1 : 0;
        r += (svj[r]     < u) ? 1 : 0;
        const int o = jo + r;
        acc += fmaf(u2, qA[o],
               fmaf(u,  qB[o],
               fmaf(u3, __int2float_rn(r), qC[o])));
    }
    const float logit = acc * (1.f / 32.f);

    // softmax over 128 j's: 4 warp-partials combined via smem
    float mw = wmax(logit);
    if (lane == 0) redm[rg * 4 + q] = mw;
    __syncthreads();
    const float* rm = redm + rg * 4;
    const float mx = fmaxf(fmaxf(rm[0], rm[1]), fmaxf(rm[2], rm[3]));
    const float ee = __expf(logit - mx);
    float sw = wsum(ee);
    if (lane == 0) reds[rg * 4 + q] = sw;
    __syncthreads();
    const float* rs = reds + rg * 4;
    const float inv = 1.f / ((rs[0] + rs[1]) + (rs[2] + rs[3]));
    attn[rg * 128 + j] = ee * inv;
    __syncthreads();

    // partial AV over this warp's 32 j's (lane = e)
    {
        const float* atr = attn + rg * 128 + q * 32;
        const float* xb  = xsh + q * 32 * 32;
        float a0 = 0.f, a1 = 0.f;
        #pragma unroll 8
        for (int jj = 0; jj < 32; jj += 2) {
            a0 = fmaf(atr[jj],     xb[jj * 32 + lane],       a0);
            a1 = fmaf(atr[jj + 1], xb[(jj + 1) * 32 + lane], a1);
        }
        osmp[(q * 8 + rg) * 32 + lane] = a0 + a1;
    }
    __syncthreads();

    // combine quarters + stage w_out slice into (dead) qA+qB region
    if (t < 256)
        osm[t] = (osmp[t] + osmp[256 + t]) + (osmp[512 + t] + osmp[768 + t]);
    float* wsm = qA;   // 256*33 = 8448 floats (= qA+qB)
    for (int g = t; g < 8192; g += 1024) {
        const int e = g >> 5, f = g & 31;
        wsm[e * 33 + f] = w_out[(e << 8) + (hq << 5) + f];
    }
    __syncthreads();

    // out[row, e] += sum_f osm[row][f] * w_out[e][hq*32+f]; t = (e, row-quarter)
    {
        const int e = t & 255, rh = t >> 8;
        #pragma unroll
        for (int rr = 0; rr < 2; ++rr) {
            const int r_ = rh * 2 + rr;
            const float* ob = osm + r_ * 32;
            const float* wr = wsm + e * 33;
            float acc2 = 0.f;
            #pragma unroll
            for (int k = 0; k < 8; ++k) {
                const float4 o4 = *(const float4*)(ob + 4 * k);   // broadcast LDS.128
                acc2 = fmaf(o4.x, wr[4 * k + 0],
                       fmaf(o4.y, wr[4 * k + 1],
                       fmaf(o4.z, wr[4 * k + 2],
                       fmaf(o4.w, wr[4 * k + 3], acc2))));
            }
            const int row = (bq << 7) + blockIdx.x * 8 + r_;
            atomicAdd(out + row * 256 + e, acc2);
        }
    }
}

extern "C" void kernel_launch(void* const* d_in, const int* in_sizes, int n_in,
                              void* d_out, int out_size) {
    const float* inp   = (const float*)d_in[0];
    const float* w_in  = (const float*)d_in[1];
    const float* b_in  = (const float*)d_in[2];
    const float* w_out = (const float*)d_in[3];
    const float* b_out = (const float*)d_in[4];
    float* out = (float*)d_out;
    (void)in_sizes; (void)n_in; (void)out_size;

    cudaFuncSetAttribute(k_proj,   cudaFuncAttributeMaxDynamicSharedMemorySize, SMEM_PROJ);
    cudaFuncSetAttribute(k_spline, cudaFuncAttributeMaxDynamicSharedMemorySize, SMEM_SPL);

    k_proj  <<<dim3(32, 8),  256,  SMEM_PROJ>>>(inp, w_in, b_in, b_out, out);
    k_spline<<<dim3(16, 16), 1024, SMEM_SPL>>>(w_out, out);
}

// round 15
// speedup vs baseline: 1.5289x; 1.5289x over previous
#include <cuda_runtime.h>

#define BH_ 16

// gmem scratch
__device__ float4 g_xs4[BH_ * 1024];          // softmaxed x, stride 32 floats
__device__ float  g_sv [BH_ * 128 * 33];      // sorted values, stride 33
__device__ float  g_qA [BH_ * 128 * 33];      // 1 - prefix1(r)     (coeff 0.5u^2)
__device__ float  g_qB [BH_ * 128 * 33];      // 0.5 * prefix2(r)   (coeff u)
__device__ float  g_qC [BH_ * 128 * 33];      // -prefix3(r)/6      (constant)
__device__ float  g_lg [BH_ * 128 * 128];     // scaled logits

static const int SMEM_PROJ = (8 * 256 + 32 * 257 + 8 * 32) * 4;            // 42112
static const int SMEM_TRI  = (4 * 528 + 512) * 4;                          // 10496
static const int SMEM_AV   = (4096 + 1024 + 256 + 8448) * 4;               // 55296

__device__ __forceinline__ float wmax(float v) {
    #pragma unroll
    for (int o = 16; o > 0; o >>= 1) v = fmaxf(v, __shfl_xor_sync(0xffffffffu, v, o));
    return v;
}
__device__ __forceinline__ float wsum(float v) {
    #pragma unroll
    for (int o = 16; o > 0; o >>= 1) v += __shfl_xor_sync(0xffffffffu, v, o);
    return v;
}

// ---------------------------------------------------------------------------
// K1: in-proj GEMM + softmax + counting-rank tables + out := b_out (bias init).
// grid(32,8), 256 thr.  [unchanged]
// ---------------------------------------------------------------------------
__global__ void k_proj(const float* __restrict__ inp,
                       const float* __restrict__ w_in,
                       const float* __restrict__ b_in,
                       const float* __restrict__ b_out,
                       float* __restrict__ out) {
    extern __shared__ float sm[];
    float* xs = sm;                 // [8][256]
    float* ws = sm + 8 * 256;       // [32][257]
    float* ps = ws + 32 * 257;      // [8][32]

    const int t = threadIdx.x, lane = t & 31, wid = t >> 5;
    const int r0 = blockIdx.x * 8, hd = blockIdx.y, c0 = hd * 32;

    {
        const int idx = ((blockIdx.y * 32 + blockIdx.x) << 8) + t;
        out[idx] = b_out[idx & 255];
    }

    #pragma unroll
    for (int f = t; f < 512; f += 256) {
        const int r = f >> 6, kq = f & 63;
        *(float4*)(xs + r * 256 + kq * 4) = *(const float4*)(inp + (r0 + r) * 256 + kq * 4);
    }
    #pragma unroll
    for (int rr = 0; rr < 4; ++rr) {
        const int cc = wid * 4 + rr;
        #pragma unroll
        for (int hh = 0; hh < 2; ++hh) {
            const int k4 = hh * 32 + lane;
            const float4 v = *(const float4*)(w_in + (c0 + cc) * 256 + k4 * 4);
            float* d = ws + cc * 257 + k4 * 4;
            d[0] = v.x; d[1] = v.y; d[2] = v.z; d[3] = v.w;
        }
    }
    __syncthreads();

    const int kh = wid >> 2, rg = wid & 3;
    const float* wrow = ws + lane * 257 + kh * 128;
    float acc[2] = {0.f, 0.f};
    #pragma unroll 8
    for (int kq = 0; kq < 32; ++kq) {
        const float w0 = wrow[4 * kq + 0], w1 = wrow[4 * kq + 1];
        const float w2 = wrow[4 * kq + 2], w3 = wrow[4 * kq + 3];
        #pragma unroll
        for (int rr = 0; rr < 2; ++rr) {
            const float4 x4 = *(const float4*)(xs + (rg * 2 + rr) * 256 + kh * 128 + 4 * kq);
            acc[rr] = fmaf(w0, x4.x, fmaf(w1, x4.y, fmaf(w2, x4.z, fmaf(w3, x4.w, acc[rr]))));
        }
    }
    if (kh == 1) {
        #pragma unroll
        for (int rr = 0; rr < 2; ++rr) ps[(rg * 2 + rr) * 32 + lane] = acc[rr];
    }
    __syncthreads();
    if (kh == 0) {
        const float bb = b_in[c0 + lane];
        float* gxs = (float*)g_xs4;
        #pragma unroll
        for (int rr = 0; rr < 2; ++rr) {
            const float val = acc[rr] + ps[(rg * 2 + rr) * 32 + lane] + bb;
            const float mx = wmax(val);
            float p = __expf(val - mx);
            const float smv = wsum(p);
            p = p / smv;

            const int row = r0 + rg * 2 + rr;
            const int b = row >> 7, s = row & 127;
            const int rowo = (b * 8 + hd) * 128 + s;
            gxs[rowo * 32 + lane] = p;

            const float p2o = p * p, p3o = p2o * p;
            float pre1 = 0.f, pre2 = 0.f, pre3 = 0.f;
            int rank = 0;
            #pragma unroll
            for (int f = 0; f < 32; ++f) {
                const float vf = __shfl_sync(0xffffffffu, p, f);
                const bool below = (vf < p) | ((vf == p) & (f < lane));
                if (below) {
                    const float vf2 = vf * vf;
                    pre1 += vf;
                    pre2 += vf2;
                    pre3 += vf2 * vf;
                    ++rank;
                }
            }
            g_sv[rowo * 33 + rank] = p;
            g_qA[rowo * 33 + rank] = 1.f - pre1;
            g_qB[rowo * 33 + rank] = 0.5f * pre2;
            g_qC[rowo * 33 + rank] = -pre3 * (1.f / 6.f);
            if (rank == 31) {
                g_qA[rowo * 33 + 32] = 0.f;
                g_qB[rowo * 33 + 32] = 0.5f * (pre2 + p2o);
                g_qC[rowo * 33 + 32] = -(pre3 + p3o) * (1.f / 6.f);
            }
        }
    }
}

// ---------------------------------------------------------------------------
// K2a: triangular spline logit tiles. grid(36, 16), 512 thr (16 warps).
// Tile (ti, tj) with ti <= tj, 16x16 rows each. Warp = i-row, lane = e.
// Writes scaled logit + mirror.
// ---------------------------------------------------------------------------
__global__ void __launch_bounds__(512) k_tri() {
    extern __shared__ float sm[];
    float* svs = sm;             // [16][33]
    float* qAs = svs + 528;
    float* qBs = qAs + 528;
    float* qCs = qBs + 528;
    float* ush = qCs + 528;      // [16][32]

    const int t = threadIdx.x, lane = t & 31, w = t >> 5;
    const int bh = blockIdx.y;
    int ti = 0, rem = blockIdx.x;
    while (rem >= 8 - ti) { rem -= 8 - ti; ++ti; }
    const int tj = ti + rem;
    const int i0 = ti * 16, j0 = tj * 16;

    {
        const float* bS = g_sv + bh * 4224 + j0 * 33;
        const float* bA = g_qA + bh * 4224 + j0 * 33;
        const float* bB = g_qB + bh * 4224 + j0 * 33;
        const float* bC = g_qC + bh * 4224 + j0 * 33;
        for (int f = t; f < 528; f += 512) {
            svs[f] = bS[f];
            qAs[f] = bA[f];
            qBs[f] = bB[f];
            qCs[f] = bC[f];
        }
        if (t < 128) *(float4*)(ush + 4 * t) = g_xs4[bh * 1024 + i0 * 8 + t];
    }
    __syncthreads();

    const float u  = ush[w * 32 + lane];
    const float uu = u * u;
    const float u2 = 0.5f * uu;
    const float u3 = uu * u * (1.f / 6.f);

    float cur[16];
    #pragma unroll
    for (int jj = 0; jj < 16; ++jj) {
        const float* svj = svs + jj * 33;
        int r = (svj[15] < u) ? 16 : 0;
        r += (svj[r + 7] < u) ? 8 : 0;
        r += (svj[r + 3] < u) ? 4 : 0;
        r += (svj[r + 1] < u) ? 2 : 0;
        const float a = svj[r], b = svj[r + 1];
        r += (int)(a < u) + (int)(b < u);
        const int o = jj * 33 + r;
        cur[jj] = fmaf(u2, qAs[o],
                  fmaf(u,  qBs[o],
                  fmaf(u3, __int2float_rn(r), qCs[o])));
    }

    // reduce over the 32 e-lanes: pre-sum bit4, then 4-level butterfly
    #pragma unroll
    for (int k = 0; k < 16; ++k)
        cur[k] += __shfl_xor_sync(0xffffffffu, cur[k], 16);
    #pragma unroll
    for (int o = 8; o > 0; o >>= 1) {
        #pragma unroll
        for (int k = 0; k < o; ++k) {
            const float keep = (lane & o) ? cur[k + o] : cur[k];
            const float give = (lane & o) ? cur[k] : cur[k + o];
            const float got = __shfl_xor_sync(0xffffffffu, give, o);
            cur[k] = keep + got;
        }
    }

    if (lane < 16) {
        const float val = cur[0] * (1.f / 32.f);
        float* LG = g_lg + bh * 16384;
        LG[(i0 + w) * 128 + j0 + lane] = val;
        if (ti != tj) LG[(j0 + lane) * 128 + i0 + w] = val;
    }
}

// ---------------------------------------------------------------------------
// K2b: per-row softmax + AV + partial out-projection. grid(16,16), 256 thr.
// ---------------------------------------------------------------------------
__global__ void __launch_bounds__(256) k_av(const float* __restrict__ w_out,
                                            float* __restrict__ out) {
    extern __shared__ float sm[];
    float* xsh  = sm;            // [128][32]
    float* attn = xsh + 4096;    // [8][128]
    float* osm  = attn + 1024;   // [8][32]
    float* wsm  = osm + 256;     // [256][33]

    const int t = threadIdx.x, lane = t & 31, wid = t >> 5;
    const int bh = blockIdx.y;
    const int bq = bh >> 3, hq = bh & 7;

    for (int f = t; f < 1024; f += 256)
        *(float4*)(xsh + 4 * f) = g_xs4[bh * 1024 + f];
    __syncthreads();

    const int i = blockIdx.x * 8 + wid;
    const float4 lg4 = *(const float4*)(g_lg + bh * 16384 + i * 128 + lane * 4);
    const float l0 = lg4.x, l1 = lg4.y, l2 = lg4.z, l3 = lg4.w;
    float mx = fmaxf(fmaxf(l0, l1), fmaxf(l2, l3));
    mx = wmax(mx);
    const float e0 = __expf(l0 - mx), e1 = __expf(l1 - mx);
    const float e2 = __expf(l2 - mx), e3 = __expf(l3 - mx);
    float s = (e0 + e1) + (e2 + e3);
    s = wsum(s);
    const float inv = 1.f / s;
    float* at = attn + wid * 128;
    *(float4*)(at + lane * 4) = make_float4(e0 * inv, e1 * inv, e2 * inv, e3 * inv);
    __syncwarp();

    // o[i, e=lane] = sum_j attn[j] * x[j, e]
    float a0 = 0.f, a1 = 0.f;
    #pragma unroll 8
    for (int j = 0; j < 128; j += 2) {
        a0 = fmaf(at[j],     xsh[j * 32 + lane],       a0);
        a1 = fmaf(at[j + 1], xsh[(j + 1) * 32 + lane], a1);
    }
    osm[wid * 32 + lane] = a0 + a1;
    __syncthreads();

    // stage w_out slice (coalesced, stride 33 -> conflict-free reads)
    for (int g = t; g < 8192; g += 256) {
        const int e = g >> 5, f = g & 31;
        wsm[e * 33 + f] = w_out[(e << 8) + (hq << 5) + f];
    }
    __syncthreads();

    // out[row, e] += sum_f osm[row][f] * w_out[e][hq*32+f]
    {
        const int e = t;
        float wreg[32];
        #pragma unroll
        for (int f = 0; f < 32; ++f) wreg[f] = wsm[e * 33 + f];

        #pragma unroll
        for (int r = 0; r < 8; ++r) {
            const float4* ob = (const float4*)(osm + r * 32);
            float acc = 0.f;
            #pragma unroll
            for (int k = 0; k < 8; ++k) {
                const float4 o4 = ob[k];
                acc = fmaf(o4.x, wreg[4 * k + 0],
                      fmaf(o4.y, wreg[4 * k + 1],
                      fmaf(o4.z, wreg[4 * k + 2],
                      fmaf(o4.w, wreg[4 * k + 3], acc))));
            }
            const int row = (bq << 7) + blockIdx.x * 8 + r;
            atomicAdd(out + row * 256 + e, acc);
        }
    }
}

extern "C" void kernel_launch(void* const* d_in, const int* in_sizes, int n_in,
                              void* d_out, int out_size) {
    const float* inp   = (const float*)d_in[0];
    const float* w_in  = (const float*)d_in[1];
    const float* b_in  = (const float*)d_in[2];
    const float* w_out = (const float*)d_in[3];
    const float* b_out = (const float*)d_in[4];
    float* out = (float*)d_out;
    (void)in_sizes; (void)n_in; (void)out_size;

    cudaFuncSetAttribute(k_proj, cudaFuncAttributeMaxDynamicSharedMemorySize, SMEM_PROJ);
    cudaFuncSetAttribute(k_tri,  cudaFuncAttributeMaxDynamicSharedMemorySize, SMEM_TRI);
    cudaFuncSetAttribute(k_av,   cudaFuncAttributeMaxDynamicSharedMemorySize, SMEM_AV);

    k_proj<<<dim3(32, 8),  256, SMEM_PROJ>>>(inp, w_in, b_in, b_out, out);
    k_tri <<<dim3(36, 16), 512, SMEM_TRI>>>();
    k_av  <<<dim3(16, 16), 256, SMEM_AV>>>(w_out, out);
}